// round 1
// baseline (speedup 1.0000x reference)
#include <cuda_runtime.h>

// Problem constants: preds [B=8, N=16, C=4, H=128, W=256] f32, gt [8,4,128,256] f32
#define CHW     131072          // C*H*W
#define NCHW    (16 * CHW)      // N*C*H*W
#define NPIX    1048576         // B*C*H*W
#define NBLK    1024
#define NTHR    256             // NBLK*NTHR*4 == NPIX

__device__ float g_partials[NBLK];

__device__ __forceinline__ void cas4(float4 &a, float4 &b) {
    float4 lo, hi;
    lo.x = fminf(a.x, b.x); hi.x = fmaxf(a.x, b.x);
    lo.y = fminf(a.y, b.y); hi.y = fmaxf(a.y, b.y);
    lo.z = fminf(a.z, b.z); hi.z = fmaxf(a.z, b.z);
    lo.w = fminf(a.w, b.w); hi.w = fmaxf(a.w, b.w);
    a = lo; b = hi;
}

__global__ __launch_bounds__(NTHR) void crps_main(const float* __restrict__ preds,
                                                  const float* __restrict__ gt) {
    const int t    = blockIdx.x * NTHR + threadIdx.x;   // 0 .. 262143
    const int b    = t >> 15;                           // t / (CHW/4)
    const int chw  = (t & 32767) << 2;                  // element offset within [C,H,W]

    const float4* pb = reinterpret_cast<const float4*>(preds + b * NCHW + chw);
    const float4  g  = *reinterpret_cast<const float4*>(gt + b * CHW + chw);

    // Front-batched ensemble loads: 16 independent LDG.128 (MLP high)
    float4 v[16];
    #pragma unroll
    for (int n = 0; n < 16; n++) v[n] = pb[n * (CHW / 4)];

    // term1: sum over ensemble of |p - g| (fma pipe, abs folds as src modifier)
    float4 t1 = make_float4(0.f, 0.f, 0.f, 0.f);
    #pragma unroll
    for (int n = 0; n < 16; n++) {
        t1.x += fabsf(v[n].x - g.x);
        t1.y += fabsf(v[n].y - g.y);
        t1.z += fabsf(v[n].z - g.z);
        t1.w += fabsf(v[n].w - g.w);
    }

    // Green's 16-input 60-comparator sorting network, component-wise
    // (sorts 4 pixels at once; 120 FMNMX/pixel on the alu pipe)
    cas4(v[0],v[1]);  cas4(v[2],v[3]);  cas4(v[4],v[5]);  cas4(v[6],v[7]);
    cas4(v[8],v[9]);  cas4(v[10],v[11]);cas4(v[12],v[13]);cas4(v[14],v[15]);
    cas4(v[0],v[2]);  cas4(v[4],v[6]);  cas4(v[8],v[10]); cas4(v[12],v[14]);
    cas4(v[1],v[3]);  cas4(v[5],v[7]);  cas4(v[9],v[11]); cas4(v[13],v[15]);
    cas4(v[0],v[4]);  cas4(v[8],v[12]); cas4(v[1],v[5]);  cas4(v[9],v[13]);
    cas4(v[2],v[6]);  cas4(v[10],v[14]);cas4(v[3],v[7]);  cas4(v[11],v[15]);
    cas4(v[0],v[8]);  cas4(v[1],v[9]);  cas4(v[2],v[10]); cas4(v[3],v[11]);
    cas4(v[4],v[12]); cas4(v[5],v[13]); cas4(v[6],v[14]); cas4(v[7],v[15]);
    cas4(v[5],v[10]); cas4(v[6],v[9]);  cas4(v[3],v[12]); cas4(v[13],v[14]);
    cas4(v[7],v[11]); cas4(v[1],v[2]);  cas4(v[4],v[8]);
    cas4(v[1],v[4]);  cas4(v[7],v[13]); cas4(v[2],v[8]);  cas4(v[11],v[14]);
    cas4(v[5],v[6]);  cas4(v[9],v[10]);
    cas4(v[2],v[4]);  cas4(v[11],v[13]);cas4(v[3],v[8]);  cas4(v[7],v[12]);
    cas4(v[6],v[8]);  cas4(v[10],v[12]);cas4(v[3],v[5]);  cas4(v[7],v[9]);
    cas4(v[3],v[4]);  cas4(v[5],v[6]);  cas4(v[7],v[8]);  cas4(v[9],v[10]);
    cas4(v[11],v[12]);
    cas4(v[6],v[7]);  cas4(v[8],v[9]);

    // term2 via sorted values: sum_{i<j}(x_j - x_i) = sum_k (2k-15) x_k
    float4 t2 = make_float4(0.f, 0.f, 0.f, 0.f);
    #pragma unroll
    for (int k = 0; k < 16; k++) {
        const float w = (float)(2 * k - 15);
        t2.x = fmaf(w, v[k].x, t2.x);
        t2.y = fmaf(w, v[k].y, t2.y);
        t2.z = fmaf(w, v[k].z, t2.z);
        t2.w = fmaf(w, v[k].w, t2.w);
    }

    // crps_pixel = term1/16 - (2*sum_{i<j})/(2*N*(N-1)); fold final 1/NPIX mean in
    const float c1 = 1.0f / (16.0f * (float)NPIX);
    const float c2 = 1.0f / (240.0f * (float)NPIX);   // N*(N-1) = 240
    float val = (t1.x + t1.y + t1.z + t1.w) * c1
              - (t2.x + t2.y + t2.z + t2.w) * c2;

    // Deterministic block reduction
    #pragma unroll
    for (int o = 16; o > 0; o >>= 1) val += __shfl_down_sync(0xffffffffu, val, o);
    __shared__ float s[NTHR / 32];
    if ((threadIdx.x & 31) == 0) s[threadIdx.x >> 5] = val;
    __syncthreads();
    if (threadIdx.x < (NTHR / 32)) {
        float x = s[threadIdx.x];
        #pragma unroll
        for (int o = (NTHR / 64); o > 0; o >>= 1) x += __shfl_down_sync(0xffu, x, o);
        if (threadIdx.x == 0) g_partials[blockIdx.x] = x;
    }
}

__global__ void crps_finish(float* __restrict__ out) {
    const int tid = threadIdx.x;  // 256 threads, NBLK = 1024 partials
    float v = g_partials[tid] + g_partials[tid + 256]
            + g_partials[tid + 512] + g_partials[tid + 768];
    #pragma unroll
    for (int o = 16; o > 0; o >>= 1) v += __shfl_down_sync(0xffffffffu, v, o);
    __shared__ float s[8];
    if ((tid & 31) == 0) s[tid >> 5] = v;
    __syncthreads();
    if (tid < 8) {
        float x = s[tid];
        #pragma unroll
        for (int o = 4; o > 0; o >>= 1) x += __shfl_down_sync(0xffu, x, o);
        if (tid == 0) out[0] = x;
    }
}

extern "C" void kernel_launch(void* const* d_in, const int* in_sizes, int n_in,
                              void* d_out, int out_size) {
    const float* preds = (const float*)d_in[0];  // [8,16,4,128,256]
    const float* gt    = (const float*)d_in[1];  // [8,4,128,256]
    float* out = (float*)d_out;                  // scalar f32
    (void)in_sizes; (void)n_in; (void)out_size;
    crps_main<<<NBLK, NTHR>>>(preds, gt);
    crps_finish<<<1, 256>>>(out);
}